// round 6
// baseline (speedup 1.0000x reference)
#include <cuda_runtime.h>
#include <math.h>

// ---------------- problem constants ----------------
#define NB    64
#define NPGc  50
#define EPGc  2048
#define NNODE (NB*NPGc)     // 3200
#define NEDGE (NB*EPGc)     // 131072
#define DLIN  1024
#define DCONV 12544
#define DREL  256
#define PP    50
#define KK    10
#define XX    100
#define NPAD  64            // padded node row; covers tx*4 up to 60 (c>=50 discarded)

#define CONV_SPLIT 16       // 12544/16 = 784 (mult of 16)
#define LIN_SPLIT  4        // 1024/4   = 256
#define NPARTS (CONV_SPLIT + LIN_SPLIT)
#define PARTSZ (NNODE*64)
#define MT 128              // M tile

// ---------------- scratch (static device mem; no allocs) ----------------
__device__ float g_node[NNODE*NPAD];
__device__ float g_parts[NPARTS*PARTSZ];
__device__ unsigned long long g_best[NB*PP];   // packed (enc(val)<<32 | (2047-e_local))
__device__ int   g_src[NEDGE];
__device__ int   g_dst[NEDGE];
__device__ float g_Lnode[PP];
__device__ float g_Lrel[PP];

// ---------------- helpers ----------------
__device__ __forceinline__ unsigned long long pk2(float x, float y) {
    unsigned long long r;
    asm("mov.b64 %0,{%1,%2};" : "=l"(r) : "f"(x), "f"(y));
    return r;
}
__device__ __forceinline__ void up2(unsigned long long v, float& a, float& b) {
    asm("mov.b64 {%0,%1},%2;" : "=f"(a), "=f"(b) : "l"(v));
}
__device__ __forceinline__ unsigned long long fma2(unsigned long long a,
                                                   unsigned long long b,
                                                   unsigned long long c) {
    unsigned long long d;
    asm("fma.rn.f32x2 %0,%1,%2,%3;" : "=l"(d) : "l"(a), "l"(b), "l"(c));
    return d;
}
// monotonic unsigned encoding of float
__device__ __forceinline__ unsigned fenc(float f) {
    unsigned u = __float_as_uint(f);
    return (u & 0x80000000u) ? ~u : (u | 0x80000000u);
}
__device__ __forceinline__ float fdec(unsigned u) {
    unsigned v = (u & 0x80000000u) ? (u ^ 0x80000000u) : ~u;
    return __uint_as_float(v);
}

// ---------------- kernel: normalize relation_indexes (int64 OR int32) + init ----------------
__global__ void normalize_ri_kernel(const int* __restrict__ RIw) {
    long long i = (long long)blockIdx.x * blockDim.x + threadIdx.x;
    bool is64 = true;
#pragma unroll
    for (int j = 0; j < 64; j++) is64 &= (RIw[2*j + 1] == 0);
    if (i < NEDGE) {
        if (is64) {
            g_src[i] = RIw[2*i];
            g_dst[i] = RIw[2*(NEDGE + i)];
        } else {
            g_src[i] = RIw[i];
            g_dst[i] = RIw[NEDGE + i];
        }
    }
    if (i < NB * PP) g_best[i] = 0ull;
}

// ---------------- kernel: L1 column norms ----------------
__global__ void l1_kernel(const float* __restrict__ Wobj,
                          const float* __restrict__ Wconv,
                          const float* __restrict__ Wrel) {
    int c = blockIdx.x;
    int t = threadIdx.x;
    float sn = 0.f, sr = 0.f;
    for (int k = t; k < DLIN;  k += 256) sn += fabsf(Wobj [k*PP + c]);
    for (int k = t; k < DCONV; k += 256) sn += fabsf(Wconv[k*PP + c]);
    for (int k = t; k < DREL;  k += 256) sr += fabsf(Wrel [k*PP + c]);
    __shared__ float sh1[256], sh2[256];
    sh1[t] = sn; sh2[t] = sr;
    __syncthreads();
    for (int off = 128; off; off >>= 1) {
        if (t < off) { sh1[t] += sh1[t+off]; sh2[t] += sh2[t+off]; }
        __syncthreads();
    }
    if (t == 0) { g_Lnode[c] = sh1[0]; g_Lrel[c] = sh2[0]; }
}

// ======= pair-packed GEMM mainloop =======
// As[k][m]: m-contiguous -> LDS.128 = 2 (m,m+1) pairs, no movs.
// Ws[k][2n]: duplicated (w,w) pairs -> LDS.128 = 2 broadcast pairs, no movs.
// acc[mp][n] = pair (C[2mp][n], C[2mp+1][n])

// ---------------- kernel: node GEMM (split-K, conv+lin merged) ----------------
__global__ void __launch_bounds__(256)
node_gemm_kernel(const float* __restrict__ Aconv, const float* __restrict__ Wconv,
                 const float* __restrict__ Alin,  const float* __restrict__ Wlin) {
    int m0 = blockIdx.x * MT;
    const float* A; const float* W; int Kdim, kstart, kend;
    if (blockIdx.y < CONV_SPLIT) {
        A = Aconv; W = Wconv; Kdim = DCONV;
        kstart = blockIdx.y * (DCONV / CONV_SPLIT);
        kend = kstart + (DCONV / CONV_SPLIT);
    } else {
        A = Alin; W = Wlin; Kdim = DLIN;
        kstart = (blockIdx.y - CONV_SPLIT) * (DLIN / LIN_SPLIT);
        kend = kstart + (DLIN / LIN_SPLIT);
    }
    float* out = g_parts + (size_t)blockIdx.y * PARTSZ;

    __shared__ float As[16][132];
    __shared__ float Ws[16][132];
    int tid = threadIdx.x;
    int tx = tid & 15, ty = tid >> 4;

    unsigned long long acc[4][4];
#pragma unroll
    for (int i = 0; i < 4; i++)
#pragma unroll
        for (int j = 0; j < 4; j++) acc[i][j] = pk2(0.f, 0.f);

    int ar = tid >> 2, aq = tid & 3;          // A loader: rows ar, ar+64; k-quarter aq
    int wk = tid >> 4, wn0 = (tid & 15) * 4;  // W loader

    float4 avr0, avr1; float wv0, wv1, wv2, wv3;
    {
        const float* ap = &A[(size_t)(m0 + ar) * Kdim + kstart + aq * 4];
        avr0 = *(const float4*)ap;
        avr1 = *(const float4*)(ap + (size_t)64 * Kdim);
        const float* wp = &W[(size_t)(kstart + wk) * PP + wn0];
        wv0 = (wn0 + 0 < PP) ? wp[0] : 0.f;
        wv1 = (wn0 + 1 < PP) ? wp[1] : 0.f;
        wv2 = (wn0 + 2 < PP) ? wp[2] : 0.f;
        wv3 = (wn0 + 3 < PP) ? wp[3] : 0.f;
    }

    for (int kt = kstart; kt < kend; kt += 16) {
        As[aq*4+0][ar] = avr0.x; As[aq*4+1][ar] = avr0.y;
        As[aq*4+2][ar] = avr0.z; As[aq*4+3][ar] = avr0.w;
        As[aq*4+0][ar+64] = avr1.x; As[aq*4+1][ar+64] = avr1.y;
        As[aq*4+2][ar+64] = avr1.z; As[aq*4+3][ar+64] = avr1.w;
        *(float4*)&Ws[wk][wn0*2]     = make_float4(wv0, wv0, wv1, wv1);
        *(float4*)&Ws[wk][wn0*2 + 4] = make_float4(wv2, wv2, wv3, wv3);
        __syncthreads();

        int ktn = kt + 16;
        if (ktn < kend) {
            const float* ap = &A[(size_t)(m0 + ar) * Kdim + ktn + aq * 4];
            avr0 = *(const float4*)ap;
            avr1 = *(const float4*)(ap + (size_t)64 * Kdim);
            const float* wp = &W[(size_t)(ktn + wk) * PP + wn0];
            wv0 = (wn0 + 0 < PP) ? wp[0] : 0.f;
            wv1 = (wn0 + 1 < PP) ? wp[1] : 0.f;
            wv2 = (wn0 + 2 < PP) ? wp[2] : 0.f;
            wv3 = (wn0 + 3 < PP) ? wp[3] : 0.f;
        }

#pragma unroll
        for (int kk = 0; kk < 16; kk++) {
            ulonglong2 a01 = *(const ulonglong2*)&As[kk][ty*8];
            ulonglong2 a23 = *(const ulonglong2*)&As[kk][ty*8 + 4];
            ulonglong2 w01 = *(const ulonglong2*)&Ws[kk][tx*8];
            ulonglong2 w23 = *(const ulonglong2*)&Ws[kk][tx*8 + 4];
            acc[0][0] = fma2(a01.x, w01.x, acc[0][0]);
            acc[0][1] = fma2(a01.x, w01.y, acc[0][1]);
            acc[0][2] = fma2(a01.x, w23.x, acc[0][2]);
            acc[0][3] = fma2(a01.x, w23.y, acc[0][3]);
            acc[1][0] = fma2(a01.y, w01.x, acc[1][0]);
            acc[1][1] = fma2(a01.y, w01.y, acc[1][1]);
            acc[1][2] = fma2(a01.y, w23.x, acc[1][2]);
            acc[1][3] = fma2(a01.y, w23.y, acc[1][3]);
            acc[2][0] = fma2(a23.x, w01.x, acc[2][0]);
            acc[2][1] = fma2(a23.x, w01.y, acc[2][1]);
            acc[2][2] = fma2(a23.x, w23.x, acc[2][2]);
            acc[2][3] = fma2(a23.x, w23.y, acc[2][3]);
            acc[3][0] = fma2(a23.y, w01.x, acc[3][0]);
            acc[3][1] = fma2(a23.y, w01.y, acc[3][1]);
            acc[3][2] = fma2(a23.y, w23.x, acc[3][2]);
            acc[3][3] = fma2(a23.y, w23.y, acc[3][3]);
        }
        __syncthreads();
    }
#pragma unroll
    for (int i = 0; i < 4; i++) {
        float l0,h0,l1,h1,l2,h2,l3,h3;
        up2(acc[i][0], l0, h0); up2(acc[i][1], l1, h1);
        up2(acc[i][2], l2, h2); up2(acc[i][3], l3, h3);
        int m = m0 + ty*8 + 2*i;
        *(float4*)&out[(size_t)m * 64 + tx*4]       = make_float4(l0, l1, l2, l3);
        *(float4*)&out[(size_t)(m+1) * 64 + tx*4]   = make_float4(h0, h1, h2, h3);
    }
}

// ---------------- kernel: reduce partials into node[N][NPAD] ----------------
__global__ void reduce_node_kernel() {
    int idx = blockIdx.x * blockDim.x + threadIdx.x;
    if (idx >= NNODE * PP) return;
    int n = idx / PP, c = idx % PP;
    float s = 0.f;
#pragma unroll
    for (int p = 0; p < NPARTS; p++) s += g_parts[(size_t)p * PARTSZ + n*64 + c];
    g_node[n*NPAD + c] = s;
}

// ---------------- kernel: rel GEMM + direct gather + per-(b,class) arg/max ----------------
__global__ void __launch_bounds__(256)
rel_edge_kernel(const float* __restrict__ A,          // rel_lin [E,256]
                const float* __restrict__ W) {        // W_rel [256,50]
    int m0 = blockIdx.x * MT;
    int b = m0 / EPGc;
    int e0 = m0 - b * EPGc;        // local edge base within batch

    __shared__ float As[16][132];
    __shared__ float Ws[16][132];
    __shared__ float smx[16][64];
    __shared__ int   six[16][64];

    int tid = threadIdx.x;
    int tx = tid & 15, ty = tid >> 4;

    unsigned long long acc[4][4];
#pragma unroll
    for (int i = 0; i < 4; i++)
#pragma unroll
        for (int j = 0; j < 4; j++) acc[i][j] = pk2(0.f, 0.f);

    int ar = tid >> 2, aq = tid & 3;
    int wk = tid >> 4, wn0 = (tid & 15) * 4;

    float4 avr0, avr1; float wv0, wv1, wv2, wv3;
    {
        const float* ap = &A[(size_t)(m0 + ar) * DREL + aq * 4];
        avr0 = *(const float4*)ap;
        avr1 = *(const float4*)(ap + (size_t)64 * DREL);
        const float* wp = &W[(size_t)wk * PP + wn0];
        wv0 = (wn0 + 0 < PP) ? wp[0] : 0.f;
        wv1 = (wn0 + 1 < PP) ? wp[1] : 0.f;
        wv2 = (wn0 + 2 < PP) ? wp[2] : 0.f;
        wv3 = (wn0 + 3 < PP) ? wp[3] : 0.f;
    }

    for (int kt = 0; kt < DREL; kt += 16) {
        As[aq*4+0][ar] = avr0.x; As[aq*4+1][ar] = avr0.y;
        As[aq*4+2][ar] = avr0.z; As[aq*4+3][ar] = avr0.w;
        As[aq*4+0][ar+64] = avr1.x; As[aq*4+1][ar+64] = avr1.y;
        As[aq*4+2][ar+64] = avr1.z; As[aq*4+3][ar+64] = avr1.w;
        *(float4*)&Ws[wk][wn0*2]     = make_float4(wv0, wv0, wv1, wv1);
        *(float4*)&Ws[wk][wn0*2 + 4] = make_float4(wv2, wv2, wv3, wv3);
        __syncthreads();

        int ktn = kt + 16;
        if (ktn < DREL) {
            const float* ap = &A[(size_t)(m0 + ar) * DREL + ktn + aq * 4];
            avr0 = *(const float4*)ap;
            avr1 = *(const float4*)(ap + (size_t)64 * DREL);
            const float* wp = &W[(size_t)(ktn + wk) * PP + wn0];
            wv0 = (wn0 + 0 < PP) ? wp[0] : 0.f;
            wv1 = (wn0 + 1 < PP) ? wp[1] : 0.f;
            wv2 = (wn0 + 2 < PP) ? wp[2] : 0.f;
            wv3 = (wn0 + 3 < PP) ? wp[3] : 0.f;
        }

#pragma unroll
        for (int kk = 0; kk < 16; kk++) {
            ulonglong2 a01 = *(const ulonglong2*)&As[kk][ty*8];
            ulonglong2 a23 = *(const ulonglong2*)&As[kk][ty*8 + 4];
            ulonglong2 w01 = *(const ulonglong2*)&Ws[kk][tx*8];
            ulonglong2 w23 = *(const ulonglong2*)&Ws[kk][tx*8 + 4];
            acc[0][0] = fma2(a01.x, w01.x, acc[0][0]);
            acc[0][1] = fma2(a01.x, w01.y, acc[0][1]);
            acc[0][2] = fma2(a01.x, w23.x, acc[0][2]);
            acc[0][3] = fma2(a01.x, w23.y, acc[0][3]);
            acc[1][0] = fma2(a01.y, w01.x, acc[1][0]);
            acc[1][1] = fma2(a01.y, w01.y, acc[1][1]);
            acc[1][2] = fma2(a01.y, w23.x, acc[1][2]);
            acc[1][3] = fma2(a01.y, w23.y, acc[1][3]);
            acc[2][0] = fma2(a23.x, w01.x, acc[2][0]);
            acc[2][1] = fma2(a23.x, w01.y, acc[2][1]);
            acc[2][2] = fma2(a23.x, w23.x, acc[2][2]);
            acc[2][3] = fma2(a23.x, w23.y, acc[2][3]);
            acc[3][0] = fma2(a23.y, w01.x, acc[3][0]);
            acc[3][1] = fma2(a23.y, w01.y, acc[3][1]);
            acc[3][2] = fma2(a23.y, w23.x, acc[3][2]);
            acc[3][3] = fma2(a23.y, w23.y, acc[3][3]);
        }
        __syncthreads();
    }

    // direct gather + per-thread argmax over its 8 rows for its 4 classes
    float bv0 = -3.4e38f, bv1 = -3.4e38f, bv2 = -3.4e38f, bv3 = -3.4e38f;
    int   bi0 = 0, bi1 = 0, bi2 = 0, bi3 = 0;
#pragma unroll
    for (int i = 0; i < 4; i++) {
        float l0,h0,l1,h1,l2,h2,l3,h3;
        up2(acc[i][0], l0, h0); up2(acc[i][1], l1, h1);
        up2(acc[i][2], l2, h2); up2(acc[i][3], l3, h3);
#pragma unroll
        for (int half = 0; half < 2; half++) {
            int r = 2*i + half;
            int e = m0 + ty*8 + r;
            int s = g_src[e], d = g_dst[e];
            float4 nsA = *(const float4*)&g_node[s*NPAD + tx*4];
            float4 nsB = *(const float4*)&g_node[d*NPAD + tx*4];
            float v0 = (half ? h0 : l0) + nsA.x + nsB.x;
            float v1 = (half ? h1 : l1) + nsA.y + nsB.y;
            float v2 = (half ? h2 : l2) + nsA.z + nsB.z;
            float v3 = (half ? h3 : l3) + nsA.w + nsB.w;
            if (v0 > bv0) { bv0 = v0; bi0 = r; }
            if (v1 > bv1) { bv1 = v1; bi1 = r; }
            if (v2 > bv2) { bv2 = v2; bi2 = r; }
            if (v3 > bv3) { bv3 = v3; bi3 = r; }
        }
    }
    smx[ty][tx*4+0] = bv0; six[ty][tx*4+0] = ty*8 + bi0;
    smx[ty][tx*4+1] = bv1; six[ty][tx*4+1] = ty*8 + bi1;
    smx[ty][tx*4+2] = bv2; six[ty][tx*4+2] = ty*8 + bi2;
    smx[ty][tx*4+3] = bv3; six[ty][tx*4+3] = ty*8 + bi3;
    __syncthreads();
    if (ty == 0) {
#pragma unroll
        for (int j = 0; j < 4; j++) {
            int c = tx*4 + j;
            if (c < PP) {
                float bv = smx[0][c]; int bi = six[0][c];
#pragma unroll
                for (int r = 1; r < 16; r++) {
                    if (smx[r][c] > bv) { bv = smx[r][c]; bi = six[r][c]; }
                }
                unsigned long long pkd =
                    ((unsigned long long)fenc(bv) << 32) |
                    (unsigned long long)(unsigned)(EPGc - 1 - (e0 + bi));
                atomicMax(&g_best[b*PP + c], pkd);
            }
        }
    }
}

// ---------------- kernel: topk + score + top-100 assembly ----------------
__global__ void finalize_kernel(float* __restrict__ out) {
    int b = threadIdx.x;
    if (b >= NB) return;

    float pr[PP];
    int   am[PP];
    for (int c = 0; c < PP; c++) {
        unsigned long long pkd = g_best[b*PP + c];
        float l = fdec((unsigned)(pkd >> 32));
        pr[c] = 1.f / (1.f + expf(-l));
        am[c] = EPGc - 1 - (int)(pkd & 0xFFFFFFFFull);
    }
    float scoreK[KK]; int classK[KK]; int argmK[KK];
    for (int k = 0; k < KK; k++) {
        float bvv = -1.f; int bc = 0;
        for (int c = 0; c < PP; c++)
            if (pr[c] > bvv) { bvv = pr[c]; bc = c; }
        scoreK[k] = bvv; classK[k] = bc; argmK[k] = am[bc];
        pr[bc] = -1.f;
    }

    float vals[KK];
    int   fidx[KK];
    for (int k = 0; k < KK; k++) {
        int c = classK[k];
        float s = scoreK[k];
        int el = argmK[k];
        int eg = b * EPGc + el;
        int sN = g_src[eg], dN = g_dst[eg];
        float g = s * (1.f - s);
        float Ln = g_Lnode[c], Lr = g_Lrel[c];
        float m = (sN == dN) ? 4.f : 1.f;
        vals[k] = g * g * g * s * m * Ln * Ln * Lr;
        fidx[k] = el * KK + k;
    }
    int ord[KK];
    for (int k = 0; k < KK; k++) ord[k] = k;
    for (int i = 0; i < KK; i++)
        for (int j = i + 1; j < KK; j++) {
            int a = ord[i], bb = ord[j];
            if (vals[bb] > vals[a] || (vals[bb] == vals[a] && fidx[bb] < fidx[a])) {
                ord[i] = bb; ord[j] = a;
            }
        }

    auto emit = [&](int pos, float v, int f) {
        int r = b * XX + pos;
        int el = f / KK, kq = f % KK;
        int eg = b * EPGc + el;
        out[r]          = v;
        out[6400  + r]  = (float)g_src[eg];
        out[12800 + r]  = (float)g_dst[eg];
        out[19200 + r]  = scoreK[kq];
        out[25600 + r]  = (float)classK[kq];
    };

    for (int pos = 0; pos < KK; pos++) {
        int k = ord[pos];
        emit(pos, vals[k], fidx[k]);
    }
    int pos = KK, idx = 0;
    while (pos < XX) {
        bool used = false;
        for (int k = 0; k < KK; k++) if (fidx[k] == idx) used = true;
        if (!used) { emit(pos, 0.f, idx); pos++; }
        idx++;
    }
    out[32000 + b] = (float)XX;   // n_relations
}

// ---------------- launch ----------------
extern "C" void kernel_launch(void* const* d_in, const int* in_sizes, int n_in,
                              void* d_out, int out_size) {
    const float *obj_lin = 0, *obj_conv = 0, *rel_lin = 0, *Wobj = 0, *Wconv = 0, *Wrel = 0;
    const void* RI = 0;
    for (int i = 0; i < n_in; i++) {
        switch (in_sizes[i]) {
            case 3276800:  obj_lin  = (const float*)d_in[i]; break;
            case 40140800: obj_conv = (const float*)d_in[i]; break;
            case 33554432: rel_lin  = (const float*)d_in[i]; break;
            case 262144:   RI       = d_in[i]; break;
            case 51200:    Wobj     = (const float*)d_in[i]; break;
            case 627200:   Wconv    = (const float*)d_in[i]; break;
            case 12800:    Wrel     = (const float*)d_in[i]; break;
            default: break;
        }
    }
    if (!obj_lin || !obj_conv || !rel_lin || !RI || !Wobj || !Wconv || !Wrel) {
        obj_lin  = (const float*)d_in[0];
        obj_conv = (const float*)d_in[1];
        rel_lin  = (const float*)d_in[2];
        RI       = d_in[3];
        Wobj     = (const float*)d_in[4];
        Wconv    = (const float*)d_in[5];
        Wrel     = (const float*)d_in[6];
    }
    float* out = (float*)d_out;

    normalize_ri_kernel<<<(NEDGE + 255)/256, 256>>>((const int*)RI);
    l1_kernel<<<PP, 256>>>(Wobj, Wconv, Wrel);
    node_gemm_kernel<<<dim3(NNODE/MT, NPARTS), 256>>>(obj_conv, Wconv, obj_lin, Wobj);
    reduce_node_kernel<<<(NNODE*PP + 255)/256, 256>>>();
    rel_edge_kernel<<<NEDGE/MT, 256>>>(rel_lin, Wrel);
    finalize_kernel<<<1, 64>>>(out);
}

// round 11
// speedup vs baseline: 1.1583x; 1.1583x over previous
#include <cuda_runtime.h>
#include <math.h>

// ---------------- problem constants ----------------
#define NB    64
#define NPGc  50
#define EPGc  2048
#define NNODE (NB*NPGc)     // 3200
#define NEDGE (NB*EPGc)     // 131072
#define DLIN  1024
#define DCONV 12544
#define DREL  256
#define PP    50
#define KK    10
#define XX    100

#define CONV_SPLIT 16       // 12544/16 = 784 (mult of 16)
#define LIN_SPLIT  4        // 1024/4   = 256
#define NPARTS (CONV_SPLIT + LIN_SPLIT)
#define PARTSZ (NNODE*64)
#define AS2W  152           // As2 row: 64 dup-pairs (128) + swizzle span (24)

// ---------------- scratch (static device mem; no allocs) ----------------
__device__ float g_node[NNODE*PP];
__device__ float g_parts[NPARTS*PARTSZ];
__device__ unsigned long long g_best[NB*PP];   // packed (enc(val)<<32 | (2047-e_local))
__device__ int   g_src[NEDGE];
__device__ int   g_dst[NEDGE];
__device__ float g_Lnode[PP];
__device__ float g_Lrel[PP];

// ---------------- helpers ----------------
__device__ __forceinline__ unsigned long long pk2(float x, float y) {
    unsigned long long r;
    asm("mov.b64 %0,{%1,%2};" : "=l"(r) : "f"(x), "f"(y));
    return r;
}
__device__ __forceinline__ void up2(unsigned long long v, float& a, float& b) {
    asm("mov.b64 {%0,%1},%2;" : "=f"(a), "=f"(b) : "l"(v));
}
__device__ __forceinline__ unsigned long long fma2(unsigned long long a,
                                                   unsigned long long b,
                                                   unsigned long long c) {
    unsigned long long d;
    asm("fma.rn.f32x2 %0,%1,%2,%3;" : "=l"(d) : "l"(a), "l"(b), "l"(c));
    return d;
}
// monotonic unsigned encoding of float
__device__ __forceinline__ unsigned fenc(float f) {
    unsigned u = __float_as_uint(f);
    return (u & 0x80000000u) ? ~u : (u | 0x80000000u);
}
__device__ __forceinline__ float fdec(unsigned u) {
    unsigned v = (u & 0x80000000u) ? (u ^ 0x80000000u) : ~u;
    return __uint_as_float(v);
}

// ---------------- kernel: normalize relation_indexes (int64 OR int32) + init ----------------
__global__ void normalize_ri_kernel(const int* __restrict__ RIw) {
    long long i = (long long)blockIdx.x * blockDim.x + threadIdx.x;
    bool is64 = true;
#pragma unroll
    for (int j = 0; j < 64; j++) is64 &= (RIw[2*j + 1] == 0);
    if (i < NEDGE) {
        if (is64) {
            g_src[i] = RIw[2*i];
            g_dst[i] = RIw[2*(NEDGE + i)];
        } else {
            g_src[i] = RIw[i];
            g_dst[i] = RIw[NEDGE + i];
        }
    }
    if (i < NB * PP) g_best[i] = 0ull;
}

// ---------------- kernel: L1 column norms ----------------
__global__ void l1_kernel(const float* __restrict__ Wobj,
                          const float* __restrict__ Wconv,
                          const float* __restrict__ Wrel) {
    int c = blockIdx.x;
    int t = threadIdx.x;
    float sn = 0.f, sr = 0.f;
    for (int k = t; k < DLIN;  k += 256) sn += fabsf(Wobj [k*PP + c]);
    for (int k = t; k < DCONV; k += 256) sn += fabsf(Wconv[k*PP + c]);
    for (int k = t; k < DREL;  k += 256) sr += fabsf(Wrel [k*PP + c]);
    __shared__ float sh1[256], sh2[256];
    sh1[t] = sn; sh2[t] = sr;
    __syncthreads();
    for (int off = 128; off; off >>= 1) {
        if (t < off) { sh1[t] += sh1[t+off]; sh2[t] += sh2[t+off]; }
        __syncthreads();
    }
    if (t == 0) { g_Lnode[c] = sh1[0]; g_Lrel[c] = sh2[0]; }
}

// ======= mainloop notes =======
// As2[k][2m + 8*(k>>2)]: A stored as duplicated (a,a) pairs (replaces the
// baseline's 4 pk2 MOVs per 8 FFMA2). Reads broadcast across tx -> N=1.
// Ws[k][n]: plain; LDS.128 at tx*4 (2-way, same as 375us baseline).
// acc layout identical to the 375us baseline (8x64-bit, n-pairs).

// ---------------- kernel: node GEMM (split-K, conv+lin merged) ----------------
__global__ void __launch_bounds__(256)
node_gemm_kernel(const float* __restrict__ Aconv, const float* __restrict__ Wconv,
                 const float* __restrict__ Alin,  const float* __restrict__ Wlin) {
    int m0 = blockIdx.x * 64;
    const float* A; const float* W; int Kdim, kstart, kend;
    if (blockIdx.y < CONV_SPLIT) {
        A = Aconv; W = Wconv; Kdim = DCONV;
        kstart = blockIdx.y * (DCONV / CONV_SPLIT);
        kend = kstart + (DCONV / CONV_SPLIT);
    } else {
        A = Alin; W = Wlin; Kdim = DLIN;
        kstart = (blockIdx.y - CONV_SPLIT) * (DLIN / LIN_SPLIT);
        kend = kstart + (DLIN / LIN_SPLIT);
    }
    float* out = g_parts + (size_t)blockIdx.y * PARTSZ;

    __shared__ float As2[16][AS2W];
    __shared__ float Ws[16][64];
    int tid = threadIdx.x;
    int tx = tid & 15, ty = tid >> 4;

    unsigned long long acc[4][2];
#pragma unroll
    for (int i = 0; i < 4; i++) { acc[i][0] = pk2(0.f, 0.f); acc[i][1] = acc[i][0]; }

    int ar = tid >> 2, akq = tid & 3;
    int wk = tid >> 4, wn0 = (tid & 15) * 4;
    int scol = ar*2 + 8*akq;

    float4 avr; float wvr0, wvr1, wvr2, wvr3;
    {
        int kt = kstart;
        avr = *(const float4*)&A[(size_t)(m0 + ar) * Kdim + kt + akq * 4];
        wvr0 = (wn0 + 0 < PP) ? W[(size_t)(kt + wk) * PP + wn0 + 0] : 0.f;
        wvr1 = (wn0 + 1 < PP) ? W[(size_t)(kt + wk) * PP + wn0 + 1] : 0.f;
        wvr2 = (wn0 + 2 < PP) ? W[(size_t)(kt + wk) * PP + wn0 + 2] : 0.f;
        wvr3 = (wn0 + 3 < PP) ? W[(size_t)(kt + wk) * PP + wn0 + 3] : 0.f;
    }

    for (int kt = kstart; kt < kend; kt += 16) {
        *(float2*)&As2[akq*4+0][scol] = make_float2(avr.x, avr.x);
        *(float2*)&As2[akq*4+1][scol] = make_float2(avr.y, avr.y);
        *(float2*)&As2[akq*4+2][scol] = make_float2(avr.z, avr.z);
        *(float2*)&As2[akq*4+3][scol] = make_float2(avr.w, avr.w);
        Ws[wk][wn0+0] = wvr0; Ws[wk][wn0+1] = wvr1;
        Ws[wk][wn0+2] = wvr2; Ws[wk][wn0+3] = wvr3;
        __syncthreads();

        int ktn = kt + 16;
        if (ktn < kend) {
            avr = *(const float4*)&A[(size_t)(m0 + ar) * Kdim + ktn + akq * 4];
            wvr0 = (wn0 + 0 < PP) ? W[(size_t)(ktn + wk) * PP + wn0 + 0] : 0.f;
            wvr1 = (wn0 + 1 < PP) ? W[(size_t)(ktn + wk) * PP + wn0 + 1] : 0.f;
            wvr2 = (wn0 + 2 < PP) ? W[(size_t)(ktn + wk) * PP + wn0 + 2] : 0.f;
            wvr3 = (wn0 + 3 < PP) ? W[(size_t)(ktn + wk) * PP + wn0 + 3] : 0.f;
        }

#pragma unroll
        for (int kk = 0; kk < 16; kk++) {
            const int off = 8*(kk>>2);
            ulonglong2 a01 = *(const ulonglong2*)&As2[kk][ty*8 + off];
            ulonglong2 a23 = *(const ulonglong2*)&As2[kk][ty*8 + off + 4];
            ulonglong2 wv = *(const ulonglong2*)&Ws[kk][tx*4];
            acc[0][0] = fma2(a01.x, wv.x, acc[0][0]); acc[0][1] = fma2(a01.x, wv.y, acc[0][1]);
            acc[1][0] = fma2(a01.y, wv.x, acc[1][0]); acc[1][1] = fma2(a01.y, wv.y, acc[1][1]);
            acc[2][0] = fma2(a23.x, wv.x, acc[2][0]); acc[2][1] = fma2(a23.x, wv.y, acc[2][1]);
            acc[3][0] = fma2(a23.y, wv.x, acc[3][0]); acc[3][1] = fma2(a23.y, wv.y, acc[3][1]);
        }
        __syncthreads();
    }
#pragma unroll
    for (int i = 0; i < 4; i++) {
        float4 v;
        up2(acc[i][0], v.x, v.y);
        up2(acc[i][1], v.z, v.w);
        *(float4*)&out[(size_t)(m0 + ty*4 + i) * 64 + tx*4] = v;
    }
}

// ---------------- kernel: reduce partials into node[N][50] ----------------
__global__ void reduce_node_kernel() {
    int idx = blockIdx.x * blockDim.x + threadIdx.x;
    if (idx >= NNODE * PP) return;
    int n = idx / PP, c = idx % PP;
    float s = 0.f;
#pragma unroll
    for (int p = 0; p < NPARTS; p++) s += g_parts[(size_t)p * PARTSZ + n*64 + c];
    g_node[idx] = s;
}

// ---------------- kernel: rel GEMM + gather + per-(b,class) arg/max ----------------
__global__ void __launch_bounds__(256)
rel_edge_kernel(const float* __restrict__ A,          // rel_lin [E,256]
                const float* __restrict__ W) {        // W_rel [256,50]
    int m0 = blockIdx.x * 64;
    int b = m0 / EPGc;
    int e0 = m0 - b * EPGc;        // local edge base within batch

    __shared__ float As2[16][AS2W];
    __shared__ float Ws[16][64];
    __shared__ float ns[64][52];
    __shared__ float smx[16][64];
    __shared__ int   six[16][64];

    int tid = threadIdx.x;
    int tx = tid & 15, ty = tid >> 4;

    unsigned long long acc[4][2];
#pragma unroll
    for (int i = 0; i < 4; i++) { acc[i][0] = pk2(0.f, 0.f); acc[i][1] = acc[i][0]; }

    int ar = tid >> 2, akq = tid & 3;
    int wk = tid >> 4, wn0 = (tid & 15) * 4;
    int scol = ar*2 + 8*akq;

    float4 avr; float wvr0, wvr1, wvr2, wvr3;
    avr = *(const float4*)&A[(size_t)(m0 + ar) * DREL + akq * 4];
    wvr0 = (wn0 + 0 < PP) ? W[(size_t)wk * PP + wn0 + 0] : 0.f;
    wvr1 = (wn0 + 1 < PP) ? W[(size_t)wk * PP + wn0 + 1] : 0.f;
    wvr2 = (wn0 + 2 < PP) ? W[(size_t)wk * PP + wn0 + 2] : 0.f;
    wvr3 = (wn0 + 3 < PP) ? W[(size_t)wk * PP + wn0 + 3] : 0.f;

    for (int kt = 0; kt < DREL; kt += 16) {
        *(float2*)&As2[akq*4+0][scol] = make_float2(avr.x, avr.x);
        *(float2*)&As2[akq*4+1][scol] = make_float2(avr.y, avr.y);
        *(float2*)&As2[akq*4+2][scol] = make_float2(avr.z, avr.z);
        *(float2*)&As2[akq*4+3][scol] = make_float2(avr.w, avr.w);
        Ws[wk][wn0+0] = wvr0; Ws[wk][wn0+1] = wvr1;
        Ws[wk][wn0+2] = wvr2; Ws[wk][wn0+3] = wvr3;
        __syncthreads();

        int ktn = kt + 16;
        if (ktn < DREL) {
            avr = *(const float4*)&A[(size_t)(m0 + ar) * DREL + ktn + akq * 4];
            wvr0 = (wn0 + 0 < PP) ? W[(size_t)(ktn + wk) * PP + wn0 + 0] : 0.f;
            wvr1 = (wn0 + 1 < PP) ? W[(size_t)(ktn + wk) * PP + wn0 + 1] : 0.f;
            wvr2 = (wn0 + 2 < PP) ? W[(size_t)(ktn + wk) * PP + wn0 + 2] : 0.f;
            wvr3 = (wn0 + 3 < PP) ? W[(size_t)(ktn + wk) * PP + wn0 + 3] : 0.f;
        }

#pragma unroll
        for (int kk = 0; kk < 16; kk++) {
            const int off = 8*(kk>>2);
            ulonglong2 a01 = *(const ulonglong2*)&As2[kk][ty*8 + off];
            ulonglong2 a23 = *(const ulonglong2*)&As2[kk][ty*8 + off + 4];
            ulonglong2 wv = *(const ulonglong2*)&Ws[kk][tx*4];
            acc[0][0] = fma2(a01.x, wv.x, acc[0][0]); acc[0][1] = fma2(a01.x, wv.y, acc[0][1]);
            acc[1][0] = fma2(a01.y, wv.x, acc[1][0]); acc[1][1] = fma2(a01.y, wv.y, acc[1][1]);
            acc[2][0] = fma2(a23.x, wv.x, acc[2][0]); acc[2][1] = fma2(a23.x, wv.y, acc[2][1]);
            acc[3][0] = fma2(a23.y, wv.x, acc[3][0]); acc[3][1] = fma2(a23.y, wv.y, acc[3][1]);
        }
        __syncthreads();
    }

    // gather node[src]+node[dst] for this block's 64 edges
    {
        int r = tid >> 2, q = tid & 3;
        int e = m0 + r;
        int s = g_src[e];
        int d = g_dst[e];
        for (int c = q; c < PP; c += 4)
            ns[r][c] = g_node[s*PP + c] + g_node[d*PP + c];
    }
    __syncthreads();

    float col[4][4];
#pragma unroll
    for (int i = 0; i < 4; i++) {
        up2(acc[i][0], col[i][0], col[i][1]);
        up2(acc[i][1], col[i][2], col[i][3]);
    }

    // per-thread max+argmax over its 4 rows per class (strict > => lowest idx wins)
#pragma unroll
    for (int j = 0; j < 4; j++) {
        int c = tx*4 + j;
        float bv = -3.4e38f; int bi = 0;
        if (c < PP) {
#pragma unroll
            for (int i = 0; i < 4; i++) {
                float t = col[i][j] + ns[ty*4+i][c];
                if (t > bv) { bv = t; bi = ty*4 + i; }
            }
        }
        smx[ty][c] = bv;
        six[ty][c] = bi;
    }
    __syncthreads();
    if (ty == 0) {
#pragma unroll
        for (int j = 0; j < 4; j++) {
            int c = tx*4 + j;
            if (c < PP) {
                float bv = smx[0][c]; int bi = six[0][c];
#pragma unroll
                for (int r = 1; r < 16; r++) {
                    if (smx[r][c] > bv) { bv = smx[r][c]; bi = six[r][c]; }
                }
                unsigned long long pkd =
                    ((unsigned long long)fenc(bv) << 32) |
                    (unsigned long long)(unsigned)(EPGc - 1 - (e0 + bi));
                atomicMax(&g_best[b*PP + c], pkd);
            }
        }
    }
}

// ---------------- kernel: topk + score + top-100 assembly ----------------
__global__ void finalize_kernel(float* __restrict__ out) {
    int b = threadIdx.x;
    if (b >= NB) return;

    float pr[PP];
    int   am[PP];
    for (int c = 0; c < PP; c++) {
        unsigned long long pkd = g_best[b*PP + c];
        float l = fdec((unsigned)(pkd >> 32));
        pr[c] = 1.f / (1.f + expf(-l));
        am[c] = EPGc - 1 - (int)(pkd & 0xFFFFFFFFull);
    }
    float scoreK[KK]; int classK[KK]; int argmK[KK];
    for (int k = 0; k < KK; k++) {
        float bvv = -1.f; int bc = 0;
        for (int c = 0; c < PP; c++)
            if (pr[c] > bvv) { bvv = pr[c]; bc = c; }
        scoreK[k] = bvv; classK[k] = bc; argmK[k] = am[bc];
        pr[bc] = -1.f;
    }

    float vals[KK];
    int   fidx[KK];
    for (int k = 0; k < KK; k++) {
        int c = classK[k];
        float s = scoreK[k];
        int el = argmK[k];
        int eg = b * EPGc + el;
        int sN = g_src[eg], dN = g_dst[eg];
        float g = s * (1.f - s);
        float Ln = g_Lnode[c], Lr = g_Lrel[c];
        float m = (sN == dN) ? 4.f : 1.f;
        vals[k] = g * g * g * s * m * Ln * Ln * Lr;
        fidx[k] = el * KK + k;
    }
    int ord[KK];
    for (int k = 0; k < KK; k++) ord[k] = k;
    for (int i = 0; i < KK; i++)
        for (int j = i + 1; j < KK; j++) {
            int a = ord[i], bb = ord[j];
            if (vals[bb] > vals[a] || (vals[bb] == vals[a] && fidx[bb] < fidx[a])) {
                ord[i] = bb; ord[j] = a;
            }
        }

    auto emit = [&](int pos, float v, int f) {
        int r = b * XX + pos;
        int el = f / KK, kq = f % KK;
        int eg = b * EPGc + el;
        out[r]          = v;
        out[6400  + r]  = (float)g_src[eg];
        out[12800 + r]  = (float)g_dst[eg];
        out[19200 + r]  = scoreK[kq];
        out[25600 + r]  = (float)classK[kq];
    };

    for (int pos = 0; pos < KK; pos++) {
        int k = ord[pos];
        emit(pos, vals[k], fidx[k]);
    }
    int pos = KK, idx = 0;
    while (pos < XX) {
        bool used = false;
        for (int k = 0; k < KK; k++) if (fidx[k] == idx) used = true;
        if (!used) { emit(pos, 0.f, idx); pos++; }
        idx++;
    }
    out[32000 + b] = (float)XX;   // n_relations
}

// ---------------- launch ----------------
extern "C" void kernel_launch(void* const* d_in, const int* in_sizes, int n_in,
                              void* d_out, int out_size) {
    const float *obj_lin = 0, *obj_conv = 0, *rel_lin = 0, *Wobj = 0, *Wconv = 0, *Wrel = 0;
    const void* RI = 0;
    for (int i = 0; i < n_in; i++) {
        switch (in_sizes[i]) {
            case 3276800:  obj_lin  = (const float*)d_in[i]; break;
            case 40140800: obj_conv = (const float*)d_in[i]; break;
            case 33554432: rel_lin  = (const float*)d_in[i]; break;
            case 262144:   RI       = d_in[i]; break;
            case 51200:    Wobj     = (const float*)d_in[i]; break;
            case 627200:   Wconv    = (const float*)d_in[i]; break;
            case 12800:    Wrel     = (const float*)d_in[i]; break;
            default: break;
        }
    }
    if (!obj_lin || !obj_conv || !rel_lin || !RI || !Wobj || !Wconv || !Wrel) {
        obj_lin  = (const float*)d_in[0];
        obj_conv = (const float*)d_in[1];
        rel_lin  = (const float*)d_in[2];
        RI       = d_in[3];
        Wobj     = (const float*)d_in[4];
        Wconv    = (const float*)d_in[5];
        Wrel     = (const float*)d_in[6];
    }
    float* out = (float*)d_out;

    normalize_ri_kernel<<<(NEDGE + 255)/256, 256>>>((const int*)RI);
    l1_kernel<<<PP, 256>>>(Wobj, Wconv, Wrel);
    node_gemm_kernel<<<dim3(NNODE/64, NPARTS), 256>>>(obj_conv, Wconv, obj_lin, Wobj);
    reduce_node_kernel<<<(NNODE*PP + 255)/256, 256>>>();
    rel_edge_kernel<<<NEDGE/64, 256>>>(rel_lin, Wrel);
    finalize_kernel<<<1, 64>>>(out);
}

// round 16
// speedup vs baseline: 1.3804x; 1.1917x over previous
#include <cuda_runtime.h>
#include <math.h>

// ---------------- problem constants ----------------
#define NB    64
#define NPGc  50
#define EPGc  2048
#define NNODE (NB*NPGc)     // 3200
#define NEDGE (NB*EPGc)     // 131072
#define DLIN  1024
#define DCONV 12544
#define DREL  256
#define PP    50
#define KK    10
#define XX    100

#define CONV_SPLIT 16       // 12544/16 = 784 (mult of 16)
#define LIN_SPLIT  4        // 1024/4   = 256
#define NPARTS (CONV_SPLIT + LIN_SPLIT)
#define PARTSZ (NNODE*64)

// ---------------- scratch (static device mem; no allocs) ----------------
__device__ float g_node[NNODE*PP];
__device__ float g_parts[NPARTS*PARTSZ];
__device__ unsigned long long g_best[NB*PP];   // packed (enc(val)<<32 | (2047-e_local))
__device__ int   g_src[NEDGE];
__device__ int   g_dst[NEDGE];
__device__ float g_Lnode[PP];
__device__ float g_Lrel[PP];

// ---------------- helpers ----------------
__device__ __forceinline__ unsigned long long pk2(float x, float y) {
    unsigned long long r;
    asm("mov.b64 %0,{%1,%2};" : "=l"(r) : "f"(x), "f"(y));
    return r;
}
__device__ __forceinline__ void up2(unsigned long long v, float& a, float& b) {
    asm("mov.b64 {%0,%1},%2;" : "=f"(a), "=f"(b) : "l"(v));
}
__device__ __forceinline__ unsigned long long fma2(unsigned long long a,
                                                   unsigned long long b,
                                                   unsigned long long c) {
    unsigned long long d;
    asm("fma.rn.f32x2 %0,%1,%2,%3;" : "=l"(d) : "l"(a), "l"(b), "l"(c));
    return d;
}
// monotonic unsigned encoding of float
__device__ __forceinline__ unsigned fenc(float f) {
    unsigned u = __float_as_uint(f);
    return (u & 0x80000000u) ? ~u : (u | 0x80000000u);
}
__device__ __forceinline__ float fdec(unsigned u) {
    unsigned v = (u & 0x80000000u) ? (u ^ 0x80000000u) : ~u;
    return __uint_as_float(v);
}

// ---------------- kernel: normalize relation_indexes (int64 OR int32) + init ----------------
// Little-endian int64 values < 3200 -> odd int32 words of the first row are 0.
// One probe per BLOCK (was per-thread: 8.4M redundant LDGs).
__global__ void normalize_ri_kernel(const int* __restrict__ RIw) {
    __shared__ int s_is64;
    if (threadIdx.x == 0) {
        bool is64 = true;
#pragma unroll
        for (int j = 0; j < 64; j++) is64 &= (RIw[2*j + 1] == 0);
        s_is64 = is64 ? 1 : 0;
    }
    __syncthreads();
    long long i = (long long)blockIdx.x * blockDim.x + threadIdx.x;
    if (i < NEDGE) {
        if (s_is64) {
            g_src[i] = RIw[2*i];
            g_dst[i] = RIw[2*(NEDGE + i)];
        } else {
            g_src[i] = RIw[i];
            g_dst[i] = RIw[NEDGE + i];
        }
    }
    if (i < NB * PP) g_best[i] = 0ull;
}

// ---------------- kernel: L1 column norms ----------------
__global__ void l1_kernel(const float* __restrict__ Wobj,
                          const float* __restrict__ Wconv,
                          const float* __restrict__ Wrel) {
    int c = blockIdx.x;
    int t = threadIdx.x;
    float sn = 0.f, sr = 0.f;
    for (int k = t; k < DLIN;  k += 256) sn += fabsf(Wobj [k*PP + c]);
    for (int k = t; k < DCONV; k += 256) sn += fabsf(Wconv[k*PP + c]);
    for (int k = t; k < DREL;  k += 256) sr += fabsf(Wrel [k*PP + c]);
    __shared__ float sh1[256], sh2[256];
    sh1[t] = sn; sh2[t] = sr;
    __syncthreads();
    for (int off = 128; off; off >>= 1) {
        if (t < off) { sh1[t] += sh1[t+off]; sh2[t] += sh2[t+off]; }
        __syncthreads();
    }
    if (t == 0) { g_Lnode[c] = sh1[0]; g_Lrel[c] = sh2[0]; }
}

// ======= mainloop: EXACT R3 (375us) instruction mix, + double-buffered smem =======
// One __syncthreads per K-tile (was two). Store->buf[p]; sync; prefetch; compute buf[p].
// Race-free both directions: WAR on buf[p] (iter i store vs iter i-2 compute) is
// ordered through sync_{i-1}; RAW (iter i compute vs iter i store) through sync_i.

// ---------------- kernel: node GEMM (split-K, conv+lin merged) ----------------
__global__ void __launch_bounds__(256)
node_gemm_kernel(const float* __restrict__ Aconv, const float* __restrict__ Wconv,
                 const float* __restrict__ Alin,  const float* __restrict__ Wlin) {
    int m0 = blockIdx.x * 64;
    const float* A; const float* W; int Kdim, kstart, kend;
    if (blockIdx.y < CONV_SPLIT) {
        A = Aconv; W = Wconv; Kdim = DCONV;
        kstart = blockIdx.y * (DCONV / CONV_SPLIT);
        kend = kstart + (DCONV / CONV_SPLIT);
    } else {
        A = Alin; W = Wlin; Kdim = DLIN;
        kstart = (blockIdx.y - CONV_SPLIT) * (DLIN / LIN_SPLIT);
        kend = kstart + (DLIN / LIN_SPLIT);
    }
    float* out = g_parts + (size_t)blockIdx.y * PARTSZ;

    __shared__ float As[2][16][68];
    __shared__ float Ws[2][16][64];
    int tid = threadIdx.x;
    int tx = tid & 15, ty = tid >> 4;

    unsigned long long acc[4][2];
#pragma unroll
    for (int i = 0; i < 4; i++) { acc[i][0] = pk2(0.f, 0.f); acc[i][1] = acc[i][0]; }

    int ar = tid >> 2, akq = tid & 3;
    int wk = tid >> 4, wn0 = (tid & 15) * 4;

    // prefetch first tile into registers
    float4 avr; float wvr0, wvr1, wvr2, wvr3;
    {
        int kt = kstart;
        avr = *(const float4*)&A[(size_t)(m0 + ar) * Kdim + kt + akq * 4];
        wvr0 = (wn0 + 0 < PP) ? W[(size_t)(kt + wk) * PP + wn0 + 0] : 0.f;
        wvr1 = (wn0 + 1 < PP) ? W[(size_t)(kt + wk) * PP + wn0 + 1] : 0.f;
        wvr2 = (wn0 + 2 < PP) ? W[(size_t)(kt + wk) * PP + wn0 + 2] : 0.f;
        wvr3 = (wn0 + 3 < PP) ? W[(size_t)(kt + wk) * PP + wn0 + 3] : 0.f;
    }

    int p = 0;
    for (int kt = kstart; kt < kend; kt += 16) {
        As[p][akq*4+0][ar] = avr.x; As[p][akq*4+1][ar] = avr.y;
        As[p][akq*4+2][ar] = avr.z; As[p][akq*4+3][ar] = avr.w;
        Ws[p][wk][wn0+0] = wvr0; Ws[p][wk][wn0+1] = wvr1;
        Ws[p][wk][wn0+2] = wvr2; Ws[p][wk][wn0+3] = wvr3;
        __syncthreads();

        int ktn = kt + 16;
        if (ktn < kend) {    // prefetch next tile while computing on this one
            avr = *(const float4*)&A[(size_t)(m0 + ar) * Kdim + ktn + akq * 4];
            wvr0 = (wn0 + 0 < PP) ? W[(size_t)(ktn + wk) * PP + wn0 + 0] : 0.f;
            wvr1 = (wn0 + 1 < PP) ? W[(size_t)(ktn + wk) * PP + wn0 + 1] : 0.f;
            wvr2 = (wn0 + 2 < PP) ? W[(size_t)(ktn + wk) * PP + wn0 + 2] : 0.f;
            wvr3 = (wn0 + 3 < PP) ? W[(size_t)(ktn + wk) * PP + wn0 + 3] : 0.f;
        }

#pragma unroll
        for (int kk = 0; kk < 16; kk++) {
            float4 a = *(const float4*)&As[p][kk][ty*4];
            const unsigned long long* wr = (const unsigned long long*)&Ws[p][kk][tx*4];
            unsigned long long w01 = wr[0], w23 = wr[1];
            unsigned long long a0 = pk2(a.x, a.x), a1 = pk2(a.y, a.y);
            unsigned long long a2 = pk2(a.z, a.z), a3 = pk2(a.w, a.w);
            acc[0][0] = fma2(a0, w01, acc[0][0]); acc[0][1] = fma2(a0, w23, acc[0][1]);
            acc[1][0] = fma2(a1, w01, acc[1][0]); acc[1][1] = fma2(a1, w23, acc[1][1]);
            acc[2][0] = fma2(a2, w01, acc[2][0]); acc[2][1] = fma2(a2, w23, acc[2][1]);
            acc[3][0] = fma2(a3, w01, acc[3][0]); acc[3][1] = fma2(a3, w23, acc[3][1]);
        }
        p ^= 1;
    }
#pragma unroll
    for (int i = 0; i < 4; i++) {
        float4 v;
        up2(acc[i][0], v.x, v.y);
        up2(acc[i][1], v.z, v.w);
        *(float4*)&out[(size_t)(m0 + ty*4 + i) * 64 + tx*4] = v;
    }
}

// ---------------- kernel: reduce partials into node[N][50] ----------------
__global__ void reduce_node_kernel() {
    int idx = blockIdx.x * blockDim.x + threadIdx.x;
    if (idx >= NNODE * PP) return;
    int n = idx / PP, c = idx % PP;
    float s = 0.f;
#pragma unroll
    for (int p = 0; p < NPARTS; p++) s += g_parts[(size_t)p * PARTSZ + n*64 + c];
    g_node[idx] = s;
}

// ---------------- kernel: rel GEMM + gather + per-(b,class) arg/max ----------------
__global__ void __launch_bounds__(256)
rel_edge_kernel(const float* __restrict__ A,          // rel_lin [E,256]
                const float* __restrict__ W) {        // W_rel [256,50]
    int m0 = blockIdx.x * 64;
    int b = m0 / EPGc;
    int e0 = m0 - b * EPGc;        // local edge base within batch

    __shared__ float As[2][16][68];
    __shared__ float Ws[2][16][64];
    __shared__ float ns[64][52];
    __shared__ float smx[16][64];
    __shared__ int   six[16][64];

    int tid = threadIdx.x;
    int tx = tid & 15, ty = tid >> 4;

    unsigned long long acc[4][2];
#pragma unroll
    for (int i = 0; i < 4; i++) { acc[i][0] = pk2(0.f, 0.f); acc[i][1] = acc[i][0]; }

    int ar = tid >> 2, akq = tid & 3;
    int wk = tid >> 4, wn0 = (tid & 15) * 4;

    float4 avr; float wvr0, wvr1, wvr2, wvr3;
    avr = *(const float4*)&A[(size_t)(m0 + ar) * DREL + akq * 4];
    wvr0 = (wn0 + 0 < PP) ? W[(size_t)wk * PP + wn0 + 0] : 0.f;
    wvr1 = (wn0 + 1 < PP) ? W[(size_t)wk * PP + wn0 + 1] : 0.f;
    wvr2 = (wn0 + 2 < PP) ? W[(size_t)wk * PP + wn0 + 2] : 0.f;
    wvr3 = (wn0 + 3 < PP) ? W[(size_t)wk * PP + wn0 + 3] : 0.f;

    int p = 0;
    for (int kt = 0; kt < DREL; kt += 16) {
        As[p][akq*4+0][ar] = avr.x; As[p][akq*4+1][ar] = avr.y;
        As[p][akq*4+2][ar] = avr.z; As[p][akq*4+3][ar] = avr.w;
        Ws[p][wk][wn0+0] = wvr0; Ws[p][wk][wn0+1] = wvr1;
        Ws[p][wk][wn0+2] = wvr2; Ws[p][wk][wn0+3] = wvr3;
        __syncthreads();

        int ktn = kt + 16;
        if (ktn < DREL) {
            avr = *(const float4*)&A[(size_t)(m0 + ar) * DREL + ktn + akq * 4];
            wvr0 = (wn0 + 0 < PP) ? W[(size_t)(ktn + wk) * PP + wn0 + 0] : 0.f;
            wvr1 = (wn0 + 1 < PP) ? W[(size_t)(ktn + wk) * PP + wn0 + 1] : 0.f;
            wvr2 = (wn0 + 2 < PP) ? W[(size_t)(ktn + wk) * PP + wn0 + 2] : 0.f;
            wvr3 = (wn0 + 3 < PP) ? W[(size_t)(ktn + wk) * PP + wn0 + 3] : 0.f;
        }

#pragma unroll
        for (int kk = 0; kk < 16; kk++) {
            float4 a = *(const float4*)&As[p][kk][ty*4];
            const unsigned long long* wr = (const unsigned long long*)&Ws[p][kk][tx*4];
            unsigned long long w01 = wr[0], w23 = wr[1];
            unsigned long long a0 = pk2(a.x, a.x), a1 = pk2(a.y, a.y);
            unsigned long long a2 = pk2(a.z, a.z), a3 = pk2(a.w, a.w);
            acc[0][0] = fma2(a0, w01, acc[0][0]); acc[0][1] = fma2(a0, w23, acc[0][1]);
            acc[1][0] = fma2(a1, w01, acc[1][0]); acc[1][1] = fma2(a1, w23, acc[1][1]);
            acc[2][0] = fma2(a2, w01, acc[2][0]); acc[2][1] = fma2(a2, w23, acc[2][1]);
            acc[3][0] = fma2(a3, w01, acc[3][0]); acc[3][1] = fma2(a3, w23, acc[3][1]);
        }
        p ^= 1;
    }

    __syncthreads();   // mainloop done before ns phase below

    // gather node[src]+node[dst] for this block's 64 edges
    {
        int r = tid >> 2, q = tid & 3;
        int e = m0 + r;
        int s = g_src[e];
        int d = g_dst[e];
        for (int c = q; c < PP; c += 4)
            ns[r][c] = g_node[s*PP + c] + g_node[d*PP + c];
    }
    __syncthreads();

    float col[4][4];
#pragma unroll
    for (int i = 0; i < 4; i++) {
        up2(acc[i][0], col[i][0], col[i][1]);
        up2(acc[i][1], col[i][2], col[i][3]);
    }

    // per-thread max+argmax over its 4 rows per class (strict > => lowest idx wins)
#pragma unroll
    for (int j = 0; j < 4; j++) {
        int c = tx*4 + j;
        float bv = -3.4e38f; int bi = 0;
        if (c < PP) {
#pragma unroll
            for (int i = 0; i < 4; i++) {
                float t = col[i][j] + ns[ty*4+i][c];
                if (t > bv) { bv = t; bi = ty*4 + i; }
            }
        }
        smx[ty][c] = bv;
        six[ty][c] = bi;
    }
    __syncthreads();
    if (ty == 0) {
#pragma unroll
        for (int j = 0; j < 4; j++) {
            int c = tx*4 + j;
            if (c < PP) {
                float bv = smx[0][c]; int bi = six[0][c];
#pragma unroll
                for (int r = 1; r < 16; r++) {
                    if (smx[r][c] > bv) { bv = smx[r][c]; bi = six[r][c]; }
                }
                unsigned long long pkd =
                    ((unsigned long long)fenc(bv) << 32) |
                    (unsigned long long)(unsigned)(EPGc - 1 - (e0 + bi));
                atomicMax(&g_best[b*PP + c], pkd);
            }
        }
    }
}

// ---------------- kernel: topk + score + top-100 assembly ----------------
__global__ void finalize_kernel(float* __restrict__ out) {
    int b = threadIdx.x;
    if (b >= NB) return;

    float pr[PP];
    int   am[PP];
    for (int c = 0; c < PP; c++) {
        unsigned long long pkd = g_best[b*PP + c];
        float l = fdec((unsigned)(pkd >> 32));
        pr[c] = 1.f / (1.f + expf(-l));
        am[c] = EPGc - 1 - (int)(pkd & 0xFFFFFFFFull);
    }
    float scoreK[KK]; int classK[KK]; int argmK[KK];
    for (int k = 0; k < KK; k++) {
        float bvv = -1.f; int bc = 0;
        for (int c = 0; c < PP; c++)
            if (pr[c] > bvv) { bvv = pr[c]; bc = c; }
        scoreK[k] = bvv; classK[k] = bc; argmK[k] = am[bc];
        pr[bc] = -1.f;
    }

    float vals[KK];
    int   fidx[KK];
    for (int k = 0; k < KK; k++) {
        int c = classK[k];
        float s = scoreK[k];
        int el = argmK[k];
        int eg = b * EPGc + el;
        int sN = g_src[eg], dN = g_dst[eg];
        float g = s * (1.f - s);
        float Ln = g_Lnode[c], Lr = g_Lrel[c];
        float m = (sN == dN) ? 4.f : 1.f;
        vals[k] = g * g * g * s * m * Ln * Ln * Lr;
        fidx[k] = el * KK + k;
    }
    int ord[KK];
    for (int k = 0; k < KK; k++) ord[k] = k;
    for (int i = 0; i < KK; i++)
        for (int j = i + 1; j < KK; j++) {
            int a = ord[i], bb = ord[j];
            if (vals[bb] > vals[a] || (vals[bb] == vals[a] && fidx[bb] < fidx[a])) {
                ord[i] = bb; ord[j] = a;
            }
        }

    auto emit = [&](int pos, float v, int f) {
        int r = b * XX + pos;
        int el = f / KK, kq = f % KK;
        int eg = b * EPGc + el;
        out[r]          = v;
        out[6400  + r]  = (float)g_src[eg];
        out[12800 + r]  = (float)g_dst[eg];
        out[19200 + r]  = scoreK[kq];
        out[25600 + r]  = (float)classK[kq];
    };

    for (int pos = 0; pos < KK; pos++) {
        int k = ord[pos];
        emit(pos, vals[k], fidx[k]);
    }
    int pos = KK, idx = 0;
    while (pos < XX) {
        bool used = false;
        for (int k = 0; k < KK; k++) if (fidx[k] == idx) used = true;
        if (!used) { emit(pos, 0.f, idx); pos++; }
        idx++;
    }
    out[32000 + b] = (float)XX;   // n_relations
}

// ---------------- launch ----------------
extern "C" void kernel_launch(void* const* d_in, const int* in_sizes, int n_in,
                              void* d_out, int out_size) {
    const float *obj_lin = 0, *obj_conv = 0, *rel_lin = 0, *Wobj = 0, *Wconv = 0, *Wrel = 0;
    const void* RI = 0;
    for (int i = 0; i < n_in; i++) {
        switch (in_sizes[i]) {
            case 3276800:  obj_lin  = (const float*)d_in[i]; break;
            case 40140800: obj_conv = (const float*)d_in[i]; break;
            case 33554432: rel_lin  = (const float*)d_in[i]; break;
            case 262144:   RI       = d_in[i]; break;
            case 51200:    Wobj     = (const float*)d_in[i]; break;
            case 627200:   Wconv    = (const float*)d_in[i]; break;
            case 12800:    Wrel     = (const float*)d_in[i]; break;
            default: break;
        }
    }
    if (!obj_lin || !obj_conv || !rel_lin || !RI || !Wobj || !Wconv || !Wrel) {
        obj_lin  = (const float*)d_in[0];
        obj_conv = (const float*)d_in[1];
        rel_lin  = (const float*)d_in[2];
        RI       = d_in[3];
        Wobj     = (const float*)d_in[4];
        Wconv    = (const float*)d_in[5];
        Wrel     = (const float*)d_in[6];
    }
    float* out = (float*)d_out;

    normalize_ri_kernel<<<(NEDGE + 255)/256, 256>>>((const int*)RI);
    l1_kernel<<<PP, 256>>>(Wobj, Wconv, Wrel);
    node_gemm_kernel<<<dim3(NNODE/64, NPARTS), 256>>>(obj_conv, Wconv, obj_lin, Wobj);
    reduce_node_kernel<<<(NNODE*PP + 255)/256, 256>>>();
    rel_edge_kernel<<<NEDGE/64, 256>>>(rel_lin, Wrel);
    finalize_kernel<<<1, 64>>>(out);
}